// round 10
// baseline (speedup 1.0000x reference)
#include <cuda_runtime.h>
#include <math_constants.h>

// CropProposals: 3D ROI 2x2x2 adaptive max-pool.
// fm:      (4, 64, 24, 24, 24) f32   -> d_in[0]
// corners: (4, 64, 2, 3)       f32   -> d_in[1]
// out:     (4, 64, 64, 2, 2, 2) f32
//
// Two kernels: (1) bin_kernel computes per-(b,p) bin geometry once (256 tasks,
// one thread each) into a __device__ global; (2) main kernel = R5 structure:
// 2 warps per (b,p,c) split by fused-d parity, 4-warp blocks (2 channels x
// 2 halves) all sharing one (b,p) -> uniform duration, 8192 blocks.
// Lanes span z (clamped into the z-union -> unpredicated loads); fused
// bin0/bin1 d- and h-segments give 4 independent LDG streams with 2x unroll.
// z-binning via redux.sync on order-preserving keys; halves combined in smem.

#define NEGINF (-CUDART_INF_F)
#define KEY_NEGINF 0x007FFFFFu   // f2key(-inf)

// per (b,p) task, per axis: {blo, bmh, m, odd}; bhi = bmh + m
__device__ int4 g_bins[256 * 3];

__device__ __forceinline__ unsigned f2key(float f) {
    int i = __float_as_int(f);
    return (unsigned)(i ^ ((i >> 31) | 0x80000000));
}
__device__ __forceinline__ float key2f(unsigned u) {
    int i = (int)(u ^ ((~u >> 31) ? 0xFFFFFFFFu : 0x80000000u));
    return __int_as_float(i);
}

__global__ void bin_kernel(const float* __restrict__ corners)
{
    const int bp = threadIdx.x;            // 0..255
    const float* cor = corners + bp * 6;
#pragma unroll
    for (int a = 0; a < 3; a++) {
        float ll = __ldg(cor + a)     * 0.25f;
        float ur = __ldg(cor + 3 + a) * 0.25f;
        ll = fminf(fmaxf(ll, 0.0f), 21.0f);
        ur = (ur - ll >= 2.0f) ? ur : (ll + 2.0f);
        ur = fminf(fmaxf(ur, 2.0f), 23.0f);
        int lo = (int)floorf(ll);
        int n  = (int)floorf(ur) - lo;
        g_bins[bp * 3 + a] = make_int4(lo, lo + ((n + 1) >> 1), n >> 1, n & 1);
    }
}

__global__ __launch_bounds__(128) void crop_proposals_kernel(
    const float* __restrict__ fm,
    float* __restrict__ out)
{
    __shared__ unsigned skey[4][8];

    const int wid   = threadIdx.x >> 5;   // 0..3
    const int lane  = threadIdx.x & 31;
    const int cpair = wid >> 1;           // 0..1 : channel within block
    const int half  = wid & 1;            // 0/1  : d-parity split

    const int bp = blockIdx.x >> 5;       // b*64 + p (0..255)
    const int cg = blockIdx.x & 31;       // channel group
    const int b  = bp >> 6;
    const int c  = cg * 2 + cpair;

    // ---- load precomputed bins: 3 const LDG.128 ----
    const int4 bx = __ldg(&g_bins[bp * 3 + 0]);   // d axis
    const int4 by = __ldg(&g_bins[bp * 3 + 1]);   // h axis
    const int4 bz = __ldg(&g_bins[bp * 3 + 2]);   // z axis

    // clamp lane's z into the union [blo_z, bhi_z) -> loads always in-region
    const int zhi = bz.y + bz.z;                  // bhi_z
    const int zc  = min(max(lane, bx.x * 0 + bz.x), zhi - 1);

    const float* base = fm + ((size_t)(b * 64 + c)) * 13824 + zc;

    const int hA0 = by.x * 24;
    const int hC0 = by.y * 24;
    const int hM  = (by.x + by.z) * 24;   // middle h row (valid iff by.w)
    const int mh  = by.z;

    float a00 = NEGINF, a01 = NEGINF, a10 = NEGINF, a11 = NEGINF;

    // ---- fused main loop: this warp takes i = half, half+2, ... < m_d ----
    for (int i = half; i < bx.z; i += 2) {
        const float* pA = base + (bx.x + i) * 576;
        const float* pC = base + (bx.y + i) * 576;

        const float* qA0 = pA + hA0;
        const float* qA1 = pA + hC0;
        const float* qC0 = pC + hA0;
        const float* qC1 = pC + hC0;
        int j = 0;
        for (; j + 1 < mh; j += 2) {
            float v0 = __ldg(qA0),      v1 = __ldg(qA1);
            float v2 = __ldg(qC0),      v3 = __ldg(qC1);
            float w0 = __ldg(qA0 + 24), w1 = __ldg(qA1 + 24);
            float w2 = __ldg(qC0 + 24), w3 = __ldg(qC1 + 24);
            a00 = fmaxf(a00, fmaxf(v0, w0));
            a01 = fmaxf(a01, fmaxf(v1, w1));
            a10 = fmaxf(a10, fmaxf(v2, w2));
            a11 = fmaxf(a11, fmaxf(v3, w3));
            qA0 += 48; qA1 += 48; qC0 += 48; qC1 += 48;
        }
        if (j < mh) {
            a00 = fmaxf(a00, __ldg(qA0));
            a01 = fmaxf(a01, __ldg(qA1));
            a10 = fmaxf(a10, __ldg(qC0));
            a11 = fmaxf(a11, __ldg(qC1));
        }
        if (by.w) {        // shared middle h row -> both ky bins
            float vA = __ldg(pA + hM);
            float vC = __ldg(pC + hM);
            a00 = fmaxf(a00, vA); a01 = fmaxf(a01, vA);
            a10 = fmaxf(a10, vC); a11 = fmaxf(a11, vC);
        }
    }

    // ---- middle d slice (shared between kx bins): done by half 1 ----
    if (bx.w && half == 1) {
        const float* pM = base + (bx.x + bx.z) * 576;
        const float* q0 = pM + hA0;
        const float* q1 = pM + hC0;
        float r0 = NEGINF, r1 = NEGINF;
        int j = 0;
        for (; j + 1 < mh; j += 2) {
            float v0 = __ldg(q0), v1 = __ldg(q1);
            float w0 = __ldg(q0 + 24), w1 = __ldg(q1 + 24);
            r0 = fmaxf(r0, fmaxf(v0, w0));
            r1 = fmaxf(r1, fmaxf(v1, w1));
            q0 += 48; q1 += 48;
        }
        if (j < mh) {
            r0 = fmaxf(r0, __ldg(q0));
            r1 = fmaxf(r1, __ldg(q1));
        }
        if (by.w) {        // middle-middle voxel -> all four (kx,ky)
            float vm = __ldg(pM + hM);
            r0 = fmaxf(r0, vm);
            r1 = fmaxf(r1, vm);
        }
        a00 = fmaxf(a00, r0); a10 = fmaxf(a10, r0);
        a01 = fmaxf(a01, r1); a11 = fmaxf(a11, r1);
    }

    // ---- per-warp z-bin reductions via redux.sync on monotone keys ----
    const unsigned k00 = f2key(a00), k01 = f2key(a01);
    const unsigned k10 = f2key(a10), k11 = f2key(a11);

#pragma unroll
    for (int kz = 0; kz < 2; kz++) {
        const bool inz = kz ? (lane >= bz.x + bz.z && lane < zhi)
                            : (lane >= bz.x        && lane < bz.y);
        unsigned m00 = __reduce_max_sync(0xFFFFFFFFu, inz ? k00 : KEY_NEGINF);
        unsigned m01 = __reduce_max_sync(0xFFFFFFFFu, inz ? k01 : KEY_NEGINF);
        unsigned m10 = __reduce_max_sync(0xFFFFFFFFu, inz ? k10 : KEY_NEGINF);
        unsigned m11 = __reduce_max_sync(0xFFFFFFFFu, inz ? k11 : KEY_NEGINF);
        if (lane == 0) {
            skey[wid][kz + 0] = m00;   // slot = kx*4 + ky*2 + kz
            skey[wid][kz + 2] = m01;
            skey[wid][kz + 4] = m10;
            skey[wid][kz + 6] = m11;
        }
    }
    __syncthreads();

    // ---- combine halves + write: warp 0, lanes 0..15 ----
    if (wid == 0 && lane < 16) {
        const int ocp = lane >> 3;     // channel pair 0..1
        const int k   = lane & 7;      // output slot
        unsigned v = max(skey[ocp * 2 + 0][k], skey[ocp * 2 + 1][k]);
        const int oc = cg * 2 + ocp;
        out[(((size_t)bp * 64 + oc) << 3) + k] = key2f(v);
    }
}

extern "C" void kernel_launch(void* const* d_in, const int* in_sizes, int n_in,
                              void* d_out, int out_size)
{
    const float* fm      = (const float*)d_in[0];
    const float* corners = (const float*)d_in[1];
    float* out           = (float*)d_out;

    bin_kernel<<<1, 256>>>(corners);
    // 256 (b,p) x 32 channel-groups = 8192 blocks, 4 warps each
    crop_proposals_kernel<<<8192, 128>>>(fm, out);
}

// round 11
// speedup vs baseline: 1.4085x; 1.4085x over previous
#include <cuda_runtime.h>
#include <math_constants.h>

// CropProposals: 3D ROI 2x2x2 adaptive max-pool.
// fm:      (4, 64, 24, 24, 24) f32   -> d_in[0]
// corners: (4, 64, 2, 3)       f32   -> d_in[1]
// out:     (4, 64, 64, 2, 2, 2) f32
//
// 2-D lane mapping: W = z-union width, lane -> (hrel = lane/W, zrel = lane%W).
// Each LDG covers R = 32/W h-rows of the bin at once (~3x lane utilization).
// Per axis both bins have EQUAL length m2=(n+1)/2 starting at lo and lo+n/2
// (shared middle slice processed by both bins - idempotent under max).
// 2 warps per (b,p,c) split the d-range by parity; block = 8 warps =
// 4 channels x 2 halves sharing one (b,p) -> uniform block duration.
// z-binning via redux.sync on order-preserving keys; halves combined in smem.

#define NEGINF (-CUDART_INF_F)
#define KEY_NEGINF 0x007FFFFFu   // f2key(-inf)

__device__ __forceinline__ unsigned f2key(float f) {
    int i = __float_as_int(f);
    return (unsigned)(i ^ ((i >> 31) | 0x80000000));
}
__device__ __forceinline__ float key2f(unsigned u) {
    int i = (int)(u ^ ((~u >> 31) ? 0xFFFFFFFFu : 0x80000000u));
    return __int_as_float(i);
}

__global__ __launch_bounds__(256) void crop_proposals_kernel(
    const float* __restrict__ fm,
    const float* __restrict__ corners,
    float* __restrict__ out)
{
    __shared__ unsigned skey[8][8];

    const int wid   = threadIdx.x >> 5;   // 0..7
    const int lane  = threadIdx.x & 31;
    const int cpair = wid >> 1;           // 0..3 : channel within block
    const int half  = wid & 1;            // 0/1  : d-parity split

    const int bp = blockIdx.x >> 4;       // b*64 + p
    const int cg = blockIdx.x & 15;       // channel group
    const int b  = bp >> 6;
    const int c  = cg * 4 + cpair;

    // ---- bin computation (matches JAX _pool_masks exactly, fp32) ----
    const float* cor = corners + bp * 6;
    int blo[3], nn[3];
#pragma unroll
    for (int a = 0; a < 3; a++) {
        float ll = __ldg(cor + a)     * 0.25f;
        float ur = __ldg(cor + 3 + a) * 0.25f;
        ll = fminf(fmaxf(ll, 0.0f), 21.0f);
        ur = (ur - ll >= 2.0f) ? ur : (ll + 2.0f);
        ur = fminf(fmaxf(ur, 2.0f), 23.0f);
        int lo = (int)floorf(ll);
        blo[a] = lo;
        nn[a]  = (int)floorf(ur) - lo;   // n in [2, 23]
    }
    // equal-length bins: [lo, lo+m2) and [lo+n/2, lo+n/2+m2), m2 = (n+1)/2
    const int d0   = blo[0], md2 = (nn[0] + 1) >> 1, ddel = (nn[0] >> 1) * 576;
    const int h0   = blo[1], mh2 = (nn[1] + 1) >> 1, hseg = (nn[1] >> 1) * 24;
    const int zlo  = blo[2], mz2 = (nn[2] + 1) >> 1, zhalf = nn[2] >> 1;

    // ---- 2-D lane mapping over (h, z) ----
    const int W    = nn[2];              // z-union width (2..23)
    const int R    = 32 / W;             // h-rows per load step (1..16)
    const int hrel = lane / W;
    const int zrel = lane - hrel * W;
    const bool hv  = lane < R * W;       // lane mapped to a real (hrel, zrel)

    const float* base = fm + ((size_t)(b * 64 + c)) * 13824 + (zlo + zrel);

    float a00 = NEGINF, a01 = NEGINF, a10 = NEGINF, a11 = NEGINF;

    // ---- main loop: this warp takes d index i = half, half+2, ... < md2 ----
    for (int i = half; i < md2; i += 2) {
        const float* pA = base + (d0 + i) * 576;   // kx0 stream
        const float* pC = pA + ddel;               // kx1 stream
        for (int idx0 = 0; idx0 < mh2; idx0 += R) {
            const int idx   = idx0 + hrel;
            const bool valid = hv && (idx < mh2);
            const int ro    = (h0 + min(idx, mh2 - 1)) * 24;
            const float vA0 = __ldg(pA + ro);
            const float vA1 = __ldg(pA + ro + hseg);
            const float vC0 = __ldg(pC + ro);
            const float vC1 = __ldg(pC + ro + hseg);
            if (valid) {
                a00 = fmaxf(a00, vA0);
                a01 = fmaxf(a01, vA1);
                a10 = fmaxf(a10, vC0);
                a11 = fmaxf(a11, vC1);
            }
        }
    }

    // ---- per-warp z-bin reductions via redux.sync on monotone keys ----
    const unsigned k00 = f2key(a00), k01 = f2key(a01);
    const unsigned k10 = f2key(a10), k11 = f2key(a11);

#pragma unroll
    for (int kz = 0; kz < 2; kz++) {
        const bool inz = (unsigned)(zrel - (kz ? zhalf : 0)) < (unsigned)mz2;
        unsigned m00 = __reduce_max_sync(0xFFFFFFFFu, inz ? k00 : KEY_NEGINF);
        unsigned m01 = __reduce_max_sync(0xFFFFFFFFu, inz ? k01 : KEY_NEGINF);
        unsigned m10 = __reduce_max_sync(0xFFFFFFFFu, inz ? k10 : KEY_NEGINF);
        unsigned m11 = __reduce_max_sync(0xFFFFFFFFu, inz ? k11 : KEY_NEGINF);
        if (lane == 0) {
            skey[wid][kz + 0] = m00;   // slot = kx*4 + ky*2 + kz
            skey[wid][kz + 2] = m01;
            skey[wid][kz + 4] = m10;
            skey[wid][kz + 6] = m11;
        }
    }
    __syncthreads();

    // ---- combine halves + write: warp 0, one lane per output value ----
    if (wid == 0) {
        const int ocp = lane >> 3;     // channel pair 0..3
        const int k   = lane & 7;      // output slot kx*4+ky*2+kz
        unsigned v = max(skey[ocp * 2 + 0][k], skey[ocp * 2 + 1][k]);
        const int oc = cg * 4 + ocp;
        out[(((size_t)bp * 64 + oc) << 3) + k] = key2f(v);
    }
}

extern "C" void kernel_launch(void* const* d_in, const int* in_sizes, int n_in,
                              void* d_out, int out_size)
{
    const float* fm      = (const float*)d_in[0];
    const float* corners = (const float*)d_in[1];
    float* out           = (float*)d_out;

    // 256 (b,p) x 16 channel-groups = 4096 blocks, 8 warps each
    crop_proposals_kernel<<<4096, 256>>>(fm, corners, out);
}